// round 15
// baseline (speedup 1.0000x reference)
#include <cuda_runtime.h>
#include <math.h>

// ---------------- problem constants ----------------
#define NRBF     32
#define CUTOFF_F 5.0f
#define GAMMA_F  40.96f                 // (32/5)^2
#define STEP_F   (5.0f / 31.0f)
#define INVSTEP_F (31.0f / 5.0f)
#define PI_F     3.14159265358979323846f
#define MAXN     50000

// RBF closed-form constants: gs2 = gamma*step^2 = 1024/961 = 1.0655567
#define C2GS     13.2129032f            // 2*gamma*step
#define E1C      0.3445350f             // exp(-1*gs2)
#define E2C      0.0140906f             // exp(-4*gs2)
#define E3C      6.8410e-5f             // exp(-9*gs2)
#define E4C      3.9424e-8f             // exp(-16*gs2)

// scratch accumulator [N,16,8]
__device__ float g_agg[(size_t)MAXN * 128];

// ---------------- f32x2 packed helpers ----------------
__device__ __forceinline__ unsigned long long pack2(float lo, float hi) {
    unsigned long long r;
    asm("mov.b64 %0, {%1, %2};" : "=l"(r) : "f"(lo), "f"(hi));
    return r;
}
__device__ __forceinline__ void unpack2(unsigned long long v, float& lo, float& hi) {
    asm("mov.b64 {%0, %1}, %2;" : "=f"(lo), "=f"(hi) : "l"(v));
}
__device__ __forceinline__ void fma2(unsigned long long& d,
                                     unsigned long long a,
                                     unsigned long long b) {
    asm("fma.rn.f32x2 %0, %1, %2, %3;" : "=l"(d) : "l"(a), "l"(b), "l"(d));
}

// ---------------- fused filter + edge pass ----------------
__global__ void __launch_bounds__(256) edge_fused_kernel(
    const float* __restrict__ h,
    const float* __restrict__ pos,
    const int*   __restrict__ ei,
    const float* __restrict__ Wrbf,   // [32,16] row-major
    int E)
{
    __shared__ float sW[NRBF * 16];
    int t = threadIdx.x;
    sW[t]       = Wrbf[t];
    sW[t + 256] = Wrbf[t + 256];
    __syncthreads();

    const unsigned FULL = 0xFFFFFFFFu;
    int lane  = t & 31;
    int hlane = t & 15;
    int half  = (t >> 4) & 1;

    // ---- filter phase: 1 edge per lane ----
    int e = (blockIdx.x * 8 + (t >> 5)) * 32 + lane;
    bool valid = e < E;
    int src = 0, dst = 0;
    if (valid) { src = __ldg(ei + e); dst = __ldg(ei + E + e); }
    int packed_sd = src | (dst << 16);       // both < 65536

    float rx = 0.f, ry = 0.f, rz = 0.f;
    if (valid) {
        rx = __ldg(pos + dst * 3 + 0) - __ldg(pos + src * 3 + 0);
        ry = __ldg(pos + dst * 3 + 1) - __ldg(pos + src * 3 + 1);
        rz = __ldg(pos + dst * 3 + 2) - __ldg(pos + src * 3 + 2);
    }
    float d = sqrtf(rx * rx + ry * ry + rz * rz + 1e-12f);
    bool live = valid && (d < CUTOFF_F);
    float inv = 1.0f / d;
    float ux = rx * inv, uy = ry * inv, uz = rz * inv;

    unsigned mask = __ballot_sync(FULL, live);

    // ---- heavy phase: 2 survivors per iteration ----
    while (mask) {
        int s0 = __ffs(mask) - 1;
        unsigned m2 = mask & (mask - 1);
        int s1 = m2 ? (__ffs(m2) - 1) : 32;
        mask = m2 ? (m2 & (m2 - 1)) : 0u;

        int sl = half ? s1 : s0;
        bool act = sl < 32;
        int srcl = sl & 31;

        int   spk  = __shfl_sync(FULL, packed_sd, srcl);
        float sux  = __shfl_sync(FULL, ux,  srcl);
        float suy  = __shfl_sync(FULL, uy,  srcl);
        float suz  = __shfl_sync(FULL, uz,  srcl);
        float sd   = __shfl_sync(FULL, d,   srcl);

        if (act) {
            int ssrc = spk & 0xFFFF;
            int sdst = ((unsigned)spk) >> 16;

            // issue h-gather first; latency hides under the RBF math below
            const float4* hp = (const float4*)(h + (size_t)ssrc * 128 + hlane * 8);
            float4 A0 = __ldg(hp), A1 = __ldg(hp + 1);

            // ---- RBF weight: closed form r_{k0+m} = base * up^m * E_m ----
            int k0 = __float2int_rn(sd * INVSTEP_F);
            k0 = min(max(k0, 0), 31);
            float delta = sd - (float)k0 * STEP_F;

            float env  = 0.5f * (__cosf((PI_F / CUTOFF_F) * sd) + 1.0f);
            float base = __expf(-GAMMA_F * delta * delta) * env;
            float up   = __expf( C2GS * delta);
            float un   = 1.0f / up;

            const float* Wrow = sW + hlane;   // column c = hlane, stride 16
            float w = base * Wrow[k0 * 16];

            float t1 = base * up;
            float t2 = t1 * up, t3 = t2 * up, t4 = t3 * up;
            if (k0 + 1 <= 31) w += t1 * E1C * Wrow[(k0 + 1) * 16];
            if (k0 + 2 <= 31) w += t2 * E2C * Wrow[(k0 + 2) * 16];
            if (k0 + 3 <= 31) w += t3 * E3C * Wrow[(k0 + 3) * 16];
            if (k0 + 4 <= 31) w += t4 * E4C * Wrow[(k0 + 4) * 16];
            float n1 = base * un;
            float n2 = n1 * un, n3 = n2 * un, n4 = n3 * un;
            if (k0 - 1 >= 0) w += n1 * E1C * Wrow[(k0 - 1) * 16];
            if (k0 - 2 >= 0) w += n2 * E2C * Wrow[(k0 - 2) * 16];
            if (k0 - 3 >= 0) w += n3 * E3C * Wrow[(k0 - 3) * 16];
            if (k0 - 4 >= 0) w += n4 * E4C * Wrow[(k0 - 4) * 16];

            float wx = w * sux, wy = w * suy, wz = w * suz;

            float a0 = A0.x, a1 = A0.y, a2 = A0.z, a3 = A0.w;
            float a4 = A1.x, a5 = A1.y, a6 = A1.z, a7 = A1.w;

            float m0 = a1 * wx + a2 * wy + a3 * wz;
            float m1 = a0 * wx + a4 * wy + a5 * wz;
            float m2v= a0 * wy + a6 * wz - a4 * wx;
            float m3 = a0 * wz - a5 * wx - a6 * wy;
            float m4 = a1 * wy + a7 * wz - a2 * wx;
            float m5 = a1 * wz - a3 * wx - a7 * wy;
            float m6 = a7 * wx - a3 * wy + a2 * wz;
            float m7 = a6 * wx - a5 * wy + a4 * wz;

            float* p = g_agg + (size_t)sdst * 128 + hlane * 8;
            asm volatile("red.global.add.v4.f32 [%0], {%1,%2,%3,%4};"
                         :: "l"(p), "f"(m0), "f"(m1), "f"(m2v), "f"(m3) : "memory");
            asm volatile("red.global.add.v4.f32 [%0], {%1,%2,%3,%4};"
                         :: "l"(p + 4), "f"(m4), "f"(m5), "f"(m6), "f"(m7) : "memory");
        }
    }
}

// ---------------- node pass: double-buffered cp.async, 2 tiles/block ----------
#define NODE_STRIDE 136   // floats; 544B
#define TILE_FLOATS (32 * NODE_STRIDE)
#define NODE_SMEM_BYTES (4 * TILE_FLOATS * 4)

__device__ __forceinline__ void node_stage_tile(
    float* s_a, float* s_h,
    const float* g_a, const float* g_h,
    int nv4, int t)
{
    #pragma unroll
    for (int k = 0; k < 8; k++) {
        int idx = t + k * 128;
        if (idx < nv4) {
            int node  = idx >> 5;
            int inner = idx & 31;
            unsigned sa = (unsigned)__cvta_generic_to_shared(s_a + node * NODE_STRIDE + inner * 4);
            unsigned sh = (unsigned)__cvta_generic_to_shared(s_h + node * NODE_STRIDE + inner * 4);
            asm volatile("cp.async.cg.shared.global [%0], [%1], 16;"
                         :: "r"(sa), "l"((const float4*)g_a + idx) : "memory");
            asm volatile("cp.async.cg.shared.global [%0], [%1], 16;"
                         :: "r"(sh), "l"((const float4*)g_h + idx) : "memory");
        }
    }
}

__device__ __forceinline__ void node_compute_tile(
    const float* s_a, const float* s_h,
    const float4* s_wo4, const float4* s_wq4,
    float* __restrict__ res, int basen, int N, int t)
{
    int nl = t >> 2;
    int node = basen + nl;
    if (node < N) {
        int oo = t & 3;

        unsigned long long aacc[4][4], qacc[4][4];
        unsigned long long z = pack2(0.f, 0.f);
        #pragma unroll
        for (int j = 0; j < 4; j++)
            #pragma unroll
            for (int i = 0; i < 4; i++) { aacc[j][i] = z; qacc[j][i] = z; }

        const float* A = s_a + nl * NODE_STRIDE;
        const float* H = s_h + nl * NODE_STRIDE;

        #pragma unroll
        for (int c = 0; c < 16; c++) {
            float4 w_o = s_wo4[c * 4 + oo];
            float4 w_q = s_wq4[c * 4 + oo];
            const float4* x = (const float4*)(A + c * 8);
            const float4* y = (const float4*)(H + c * 8);
            float4 x0 = x[0], x1 = x[1];
            float4 y0 = y[0], y1 = y[1];
            unsigned long long p0 = pack2(x0.x, x0.y), p1 = pack2(x0.z, x0.w);
            unsigned long long p2 = pack2(x1.x, x1.y), p3 = pack2(x1.z, x1.w);
            unsigned long long r0 = pack2(y0.x, y0.y), r1 = pack2(y0.z, y0.w);
            unsigned long long r2 = pack2(y1.x, y1.y), r3 = pack2(y1.z, y1.w);

            float wos[4] = {w_o.x, w_o.y, w_o.z, w_o.w};
            float wqs[4] = {w_q.x, w_q.y, w_q.z, w_q.w};
            #pragma unroll
            for (int j = 0; j < 4; j++) {
                unsigned long long wo2 = pack2(wos[j], wos[j]);
                unsigned long long wq2 = pack2(wqs[j], wqs[j]);
                fma2(aacc[j][0], p0, wo2); fma2(aacc[j][1], p1, wo2);
                fma2(aacc[j][2], p2, wo2); fma2(aacc[j][3], p3, wo2);
                fma2(qacc[j][0], r0, wq2); fma2(qacc[j][1], r1, wq2);
                fma2(qacc[j][2], r2, wq2); fma2(qacc[j][3], r3, wq2);
            }
        }

        float* outbase = res + (size_t)node * 128;

        #pragma unroll
        for (int j = 0; j < 4; j++) {
            float a[8], q[8];
            #pragma unroll
            for (int i = 0; i < 4; i++) {
                unpack2(aacc[j][i], a[2 * i], a[2 * i + 1]);
                unpack2(qacc[j][i], q[2 * i], q[2 * i + 1]);
            }

            float g0 = a[0]*q[0] + a[1]*q[1] + a[2]*q[2] + a[3]*q[3] - a[4]*q[4] - a[5]*q[5] - a[6]*q[6] - a[7]*q[7];
            float g1 = a[0]*q[1] + a[1]*q[0] - a[2]*q[4] - a[3]*q[5] + a[4]*q[2] + a[5]*q[3] - a[6]*q[7] - a[7]*q[6];
            float g2 = a[0]*q[2] + a[1]*q[4] + a[2]*q[0] - a[3]*q[6] - a[4]*q[1] + a[5]*q[7] + a[6]*q[3] + a[7]*q[5];
            float g3 = a[0]*q[3] + a[1]*q[5] + a[2]*q[6] + a[3]*q[0] - a[4]*q[7] - a[5]*q[1] - a[6]*q[2] - a[7]*q[4];
            float g4 = a[0]*q[4] + a[1]*q[2] - a[2]*q[1] + a[3]*q[7] + a[4]*q[0] - a[5]*q[6] + a[6]*q[5] + a[7]*q[3];
            float g5 = a[0]*q[5] + a[1]*q[3] - a[2]*q[7] - a[3]*q[1] + a[4]*q[6] + a[5]*q[0] - a[6]*q[4] - a[7]*q[2];
            float g6 = a[0]*q[6] + a[1]*q[7] + a[2]*q[3] - a[3]*q[2] - a[4]*q[5] + a[5]*q[4] + a[6]*q[0] + a[7]*q[1];
            float g7 = a[0]*q[7] + a[1]*q[6] - a[2]*q[5] + a[3]*q[4] + a[4]*q[3] - a[5]*q[2] + a[6]*q[1] + a[7]*q[0];

            float* op = outbase + (oo + j * 4) * 8;
            ((float4*)op)[0] = make_float4(a[0] + g0, a[1] + g1, a[2] + g2, a[3] + g3);
            ((float4*)op)[1] = make_float4(a[4] + g4, a[5] + g5, a[6] + g6, a[7] + g7);
        }
    }
}

extern __shared__ float node_smem[];

__global__ void __launch_bounds__(128, 3) node_kernel(
    const float* __restrict__ h,
    const float* __restrict__ Wout,
    const float* __restrict__ Wsgp,
    float* __restrict__ res,
    int N)
{
    __shared__ float4 s_wo4[64];
    __shared__ float4 s_wq4[64];

    float* s_a0 = node_smem;
    float* s_h0 = node_smem + TILE_FLOATS;
    float* s_a1 = node_smem + 2 * TILE_FLOATS;
    float* s_h1 = node_smem + 3 * TILE_FLOATS;

    int t = threadIdx.x;
    if (t < 64) {
        int c = t >> 2, oo = t & 3;
        const float* wr = Wout + c * 16 + oo;
        const float* qr = Wsgp + c * 16 + oo;
        s_wo4[t] = make_float4(wr[0], wr[4], wr[8], wr[12]);
        s_wq4[t] = make_float4(qr[0], qr[4], qr[8], qr[12]);
    }

    int base0 = blockIdx.x * 64;
    int base1 = base0 + 32;
    int nv40 = max(0, min(32, N - base0)) * 32;
    int nv41 = max(0, min(32, N - base1)) * 32;

    node_stage_tile(s_a0, s_h0, g_agg + (size_t)base0 * 128, h + (size_t)base0 * 128, nv40, t);
    asm volatile("cp.async.commit_group;" ::: "memory");
    node_stage_tile(s_a1, s_h1, g_agg + (size_t)base1 * 128, h + (size_t)base1 * 128, nv41, t);
    asm volatile("cp.async.commit_group;" ::: "memory");

    asm volatile("cp.async.wait_group 1;" ::: "memory");
    __syncthreads();
    node_compute_tile(s_a0, s_h0, s_wo4, s_wq4, res, base0, N, t);

    asm volatile("cp.async.wait_group 0;" ::: "memory");
    __syncthreads();
    node_compute_tile(s_a1, s_h1, s_wo4, s_wq4, res, base1, N, t);
}

// ---------------- launch ----------------
extern "C" void kernel_launch(void* const* d_in, const int* in_sizes, int n_in,
                              void* d_out, int out_size)
{
    const float* h    = (const float*)d_in[0];
    const float* pos  = (const float*)d_in[1];
    const int*   ei   = (const int*)  d_in[2];
    const float* Wrbf = (const float*)d_in[3];
    const float* Wout = (const float*)d_in[4];
    const float* Wsgp = (const float*)d_in[5];
    float* out = (float*)d_out;

    int N = in_sizes[0] / 128;
    int E = in_sizes[2] / 2;
    if (N > MAXN) N = MAXN;

    void* agg_ptr = nullptr;
    cudaGetSymbolAddress(&agg_ptr, g_agg);
    cudaMemsetAsync(agg_ptr, 0, (size_t)N * 128 * sizeof(float), 0);

    cudaFuncSetAttribute(node_kernel,
                         cudaFuncAttributeMaxDynamicSharedMemorySize, NODE_SMEM_BYTES);

    int blocks = (E + 255) / 256;
    edge_fused_kernel<<<blocks, 256>>>(h, pos, ei, Wrbf, E);
    node_kernel<<<(N + 63) / 64, 128, NODE_SMEM_BYTES>>>(h, Wout, Wsgp, out, N);
}